// round 14
// baseline (speedup 1.0000x reference)
#include <cuda_runtime.h>
#include <cuda_bf16.h>
#include <math.h>
#include <stdint.h>

#define NN   50000
#define EE   800000
#define DIM  128
#define HH   8
#define HID  512
#define CATD 512

typedef __nv_bfloat16 bf16;

// ---------------- static scratch ----------------
__device__ float g_su[(size_t)NN * HH];
__device__ float g_sv[(size_t)NN * HH];
__device__ float g_ex[(size_t)EE * HH];
__device__ float g_outdeg[NN];
__device__ int   g_count[NN];
__device__ int   g_offsets[NN + 1];
__device__ int   g_cursor[NN];
__device__ int2  g_csr2[EE];
__device__ int   g_bsum[64];
__device__ float g_cw[16 * DIM];
__device__ float g_cb[16];

__device__ float g_catf[(size_t)NN * CATD];     // fp32 cat (102 MB)
__device__ float g_sca[NN];                      // cat row scales
__device__ float g_scw1[HID];                    // w1 row scales
__device__ int8_t g_catqh[(size_t)NN * CATD], g_catql[(size_t)NN * CATD];
__device__ int8_t g_w1qh[HID * CATD], g_w1ql[HID * CATD];

// bf16 hi/lo operand storage (fc + FFN2)
__device__ bf16 g_x16h[(size_t)NN * DIM],  g_x16l[(size_t)NN * DIM];
__device__ bf16 g_fh[(size_t)NN * HID],    g_fl[(size_t)NN * HID];
__device__ bf16 g_fcwh[DIM * DIM],  g_fcwl[DIM * DIM];
__device__ bf16 g_w2h[DIM * HID],   g_w2l[DIM * HID];

// ---------------- helpers ----------------
__device__ __forceinline__ uint32_t smem_u32(const void* p) {
    uint32_t a;
    asm("{ .reg .u64 t; cvta.to.shared.u64 t, %1; cvt.u32.u64 %0, t; }"
        : "=r"(a) : "l"(p));
    return a;
}
__device__ __forceinline__ void ldsm4(uint32_t* r, uint32_t addr) {
    asm volatile("ldmatrix.sync.aligned.m8n8.x4.shared.b16 {%0,%1,%2,%3}, [%4];"
                 : "=r"(r[0]), "=r"(r[1]), "=r"(r[2]), "=r"(r[3]) : "r"(addr));
}
__device__ __forceinline__ void mma16816(float* c, const uint32_t* a, const uint32_t* b) {
    asm volatile(
        "mma.sync.aligned.m16n8k16.row.col.f32.bf16.bf16.f32 "
        "{%0,%1,%2,%3}, {%4,%5,%6,%7}, {%8,%9}, {%0,%1,%2,%3};"
        : "+f"(c[0]), "+f"(c[1]), "+f"(c[2]), "+f"(c[3])
        : "r"(a[0]), "r"(a[1]), "r"(a[2]), "r"(a[3]), "r"(b[0]), "r"(b[1]));
}
__device__ __forceinline__ void mma_s8(int* c, const uint32_t* a, uint32_t b0, uint32_t b1) {
    asm volatile(
        "mma.sync.aligned.m16n8k32.row.col.s32.s8.s8.s32 "
        "{%0,%1,%2,%3}, {%4,%5,%6,%7}, {%8,%9}, {%0,%1,%2,%3};"
        : "+r"(c[0]), "+r"(c[1]), "+r"(c[2]), "+r"(c[3])
        : "r"(a[0]), "r"(a[1]), "r"(a[2]), "r"(a[3]), "r"(b0), "r"(b1));
}
__device__ __forceinline__ uint32_t pk_bf2(bf16 a, bf16 b) {
    return (uint32_t)__bfloat16_as_ushort(a) | ((uint32_t)__bfloat16_as_ushort(b) << 16);
}
__device__ __forceinline__ void cpa16(uint32_t dst, const void* src) {
    asm volatile("cp.async.ca.shared.global [%0], [%1], 16;" :: "r"(dst), "l"(src));
}
__device__ __forceinline__ void w16(bf16* hp, bf16* lp, float v) {
    bf16 h = __float2bfloat16(v);
    *hp = h;
    *lp = __float2bfloat16(v - __bfloat162float(h));
}
__device__ __forceinline__ void split4(const float* in, bf16* hi, bf16* lo, size_t i) {
    float4 v = *(const float4*)(in + i);
    bf16 h0 = __float2bfloat16(v.x), h1 = __float2bfloat16(v.y);
    bf16 h2 = __float2bfloat16(v.z), h3 = __float2bfloat16(v.w);
    uint2 H, L;
    H.x = pk_bf2(h0, h1); H.y = pk_bf2(h2, h3);
    L.x = pk_bf2(__float2bfloat16(v.x - __bfloat162float(h0)),
                 __float2bfloat16(v.y - __bfloat162float(h1)));
    L.y = pk_bf2(__float2bfloat16(v.z - __bfloat162float(h2)),
                 __float2bfloat16(v.w - __bfloat162float(h3)));
    *(uint2*)(hi + i) = H;
    *(uint2*)(lo + i) = L;
}

// ---------------- combined fp32 -> bf16 hi/lo split (x, fc_w, w2) ----------------
#define XF4   ((NN * DIM) / 4)
#define FCF4  ((DIM * DIM) / 4)
#define W2F4  ((DIM * HID) / 4)
#define TOTF4 (XF4 + FCF4 + W2F4)

__global__ void split_all(const float* __restrict__ x, const float* __restrict__ fc_w,
                          const float* __restrict__ w2) {
    int u = blockIdx.x * blockDim.x + threadIdx.x;
    if (u >= TOTF4) return;
    if (u < XF4) {
        split4(x, g_x16h, g_x16l, (size_t)u * 4);
    } else if (u < XF4 + FCF4) {
        split4(fc_w, g_fcwh, g_fcwl, (size_t)(u - XF4) * 4);
    } else {
        split4(w2, g_w2h, g_w2l, (size_t)(u - XF4 - FCF4) * 4);
    }
}

// ---------------- per-row int8 hi/lo quantization (rows of 512 f32) ----------------
// q = round(a * 16256/max) in [-16256,16256]; ah=(q+64)>>7 in [-127,127]; al=q-128*ah in [-64,63]
__global__ void quant_rows(const float* __restrict__ in, int8_t* __restrict__ qh,
                           int8_t* __restrict__ ql, float* __restrict__ sc, int rows) {
    int warp = (blockIdx.x * 256 + threadIdx.x) >> 5;
    int lane = threadIdx.x & 31;
    if (warp >= rows) return;
    const float4* r = (const float4*)(in + (size_t)warp * 512);
    float4 v[4];
    float mx = 0.f;
#pragma unroll
    for (int i = 0; i < 4; i++) {
        v[i] = r[lane * 4 + i];
        mx = fmaxf(mx, fmaxf(fmaxf(fabsf(v[i].x), fabsf(v[i].y)),
                             fmaxf(fabsf(v[i].z), fabsf(v[i].w))));
    }
#pragma unroll
    for (int o = 16; o > 0; o >>= 1)
        mx = fmaxf(mx, __shfl_xor_sync(0xffffffffu, mx, o));
    float inv = (mx > 0.f) ? (16256.f / mx) : 0.f;
    if (lane == 0) sc[warp] = mx * (1.f / 16256.f);

    uint32_t* oh = (uint32_t*)(qh + (size_t)warp * 512 + lane * 16);
    uint32_t* ol = (uint32_t*)(ql + (size_t)warp * 512 + lane * 16);
#pragma unroll
    for (int i = 0; i < 4; i++) {
        float fv[4] = {v[i].x, v[i].y, v[i].z, v[i].w};
        uint32_t ph = 0, pl = 0;
#pragma unroll
        for (int j = 0; j < 4; j++) {
            int q = __float2int_rn(fv[j] * inv);
            q = max(-16256, min(16256, q));
            int ah = (q + 64) >> 7;
            int al = q - (ah << 7);
            ph |= (uint32_t)(ah & 0xFF) << (8 * j);
            pl |= (uint32_t)(al & 0xFF) << (8 * j);
        }
        oh[i] = ph;
        ol[i] = pl;
    }
}

// ---------------- composite attention weights ----------------
__global__ void combo_w(const float* __restrict__ fc_w, const float* __restrict__ fc_b,
                        const float* __restrict__ au_w, const float* __restrict__ au_b,
                        const float* __restrict__ av_w) {
    int o = blockIdx.x;
    int d = threadIdx.x;
    const float* U = (o < 8) ? (au_w + o * DIM) : (av_w + (o - 8) * DIM);
    float acc = 0.f;
    for (int k = 0; k < DIM; k++)
        acc += U[k] * fc_w[k * DIM + d];
    g_cw[o * DIM + d] = acc;
    if (d == 0) {
        float b = 0.f;
        for (int k = 0; k < DIM; k++) b += U[k] * fc_b[k];
        if (o < 8) b += au_b[o];
        g_cb[o] = b;
    }
}

// ---------------- attention projections from x ----------------
__global__ void __launch_bounds__(256) attn2(const float* __restrict__ x) {
    __shared__ float s_w[16 * DIM];
    __shared__ float s_b[16];
    int t = threadIdx.x, lane = t & 31, warp = t >> 5;
    for (int i = t; i < 16 * DIM; i += 256) s_w[i] = g_cw[i];
    if (t < 16) s_b[t] = g_cb[t];
    __syncthreads();

    float w[16][4];
#pragma unroll
    for (int o = 0; o < 16; o++) {
        float4 ww = *(float4*)&s_w[o * DIM + lane * 4];
        w[o][0] = ww.x; w[o][1] = ww.y; w[o][2] = ww.z; w[o][3] = ww.w;
    }
    int n = blockIdx.x * 8 + warp;
    if (n >= NN) return;

    float4 v = *(const float4*)(x + (size_t)n * DIM + lane * 4);
    float p[16];
#pragma unroll
    for (int o = 0; o < 16; o++)
        p[o] = w[o][0] * v.x + w[o][1] * v.y + w[o][2] * v.z + w[o][3] * v.w;
#pragma unroll
    for (int o = 0; o < 16; o++) {
#pragma unroll
        for (int s2 = 16; s2 > 0; s2 >>= 1)
            p[o] += __shfl_xor_sync(0xffffffffu, p[o], s2);
    }
    float r = p[0];
#pragma unroll
    for (int o = 1; o < 16; o++) r = (lane == o) ? p[o] : r;
    if (lane < 8)       g_su[(size_t)n * 8 + lane]       = r + s_b[lane];
    else if (lane < 16) g_sv[(size_t)n * 8 + (lane - 8)] = r + s_b[lane];
}

// =======================================================================
// bf16x3 mma.sync GEMM — 512 threads / 16 warps (4m x 4n), warp tile 32x32.
// OUTMODE: 0 = f32 C only, 1 = bf16 hi/lo only.
// =======================================================================
#define LDK  40
#define ROWB 80
#define ARRB (128 * ROWB)
#define STGB (4 * ARRB)

template <int ACT, int OUTMODE>
__global__ void __launch_bounds__(512, 1) mma_gemm16(
    const bf16* __restrict__ Ahi, const bf16* __restrict__ Alo,
    const bf16* __restrict__ Bhi, const bf16* __restrict__ Blo,
    const float* __restrict__ bias,
    float* __restrict__ C, int ldc,
    bf16* __restrict__ Chi, bf16* __restrict__ Clo, int ldc16,
    int M, int K, int Nc)
{
    extern __shared__ char sm[];
    float* s_bias = (float*)(sm + 3 * STGB);

    const int tid  = threadIdx.x;
    const int wid  = tid >> 5;
    const int lane = tid & 31;
    const int m0 = blockIdx.y * 128;
    const int n0 = blockIdx.x * 128;
    const uint32_t sbase = smem_u32(sm);

    if (tid < 128) s_bias[tid] = bias[n0 + tid];

    const int wm = (wid >> 2) * 32;
    const int wn = (wid & 3) * 32;
    const int lrow = (lane & 7) + ((lane >> 3) & 1) * 8;
    const int lcol = (lane >> 4) * 8;

    float c[2][4][4];
#pragma unroll
    for (int i = 0; i < 2; i++)
#pragma unroll
        for (int j = 0; j < 4; j++)
#pragma unroll
            for (int r = 0; r < 4; r++) c[i][j][r] = 0.f;

    const int nchunks = K >> 5;
    const char* srcs[4] = {(const char*)Ahi, (const char*)Alo,
                           (const char*)Bhi, (const char*)Blo};

    auto load_chunk = [&](int ch, int s) {
        const int k0b = ch * 64;
#pragma unroll
        for (int t = 0; t < 4; t++) {
            int idx  = tid + t * 512;
            int unit = idx & 3;
            int row  = (idx >> 2) & 127;
            int arr  = idx >> 9;
            int grow = (arr < 2) ? min(m0 + row, M - 1) : (n0 + row);
            const char* src = srcs[arr] + (size_t)grow * (K * 2) + k0b + unit * 16;
            uint32_t dst = sbase + s * STGB + arr * ARRB + row * ROWB + unit * 16;
            cpa16(dst, src);
        }
        asm volatile("cp.async.commit_group;" ::: "memory");
    };

    load_chunk(0, 0);
    if (nchunks > 1) load_chunk(1, 1);

    for (int ch = 0; ch < nchunks; ch++) {
        if (ch + 1 < nchunks) {
            asm volatile("cp.async.wait_group 1;" ::: "memory");
        } else {
            asm volatile("cp.async.wait_group 0;" ::: "memory");
        }
        __syncthreads();
        if (ch + 2 < nchunks) load_chunk(ch + 2, (ch + 2) % 3);

        const int s = ch % 3;
        uint32_t sA_hi = sbase + s * STGB;
        uint32_t sA_lo = sA_hi + ARRB;
        uint32_t sB_hi = sA_lo + ARRB;
        uint32_t sB_lo = sB_hi + ARRB;

#pragma unroll
        for (int ks = 0; ks < 2; ks++) {
            const int kk = ks * 16;
            uint32_t ah[2][4], al[2][4], bh[4][2], bl[4][2];
#pragma unroll
            for (int mt = 0; mt < 2; mt++) {
                uint32_t off = (uint32_t)((wm + mt * 16 + lrow) * LDK + kk + lcol) * 2;
                ldsm4(ah[mt], sA_hi + off);
                ldsm4(al[mt], sA_lo + off);
            }
#pragma unroll
            for (int p = 0; p < 2; p++) {
                uint32_t off = (uint32_t)((wn + p * 16 + lrow) * LDK + kk + lcol) * 2;
                uint32_t t[4];
                ldsm4(t, sB_hi + off);
                bh[2 * p][0] = t[0]; bh[2 * p + 1][0] = t[1];
                bh[2 * p][1] = t[2]; bh[2 * p + 1][1] = t[3];
                ldsm4(t, sB_lo + off);
                bl[2 * p][0] = t[0]; bl[2 * p + 1][0] = t[1];
                bl[2 * p][1] = t[2]; bl[2 * p + 1][1] = t[3];
            }
#pragma unroll
            for (int mt = 0; mt < 2; mt++)
#pragma unroll
                for (int nt = 0; nt < 4; nt++) {
                    mma16816(c[mt][nt], ah[mt], bh[nt]);
                    mma16816(c[mt][nt], ah[mt], bl[nt]);
                    mma16816(c[mt][nt], al[mt], bh[nt]);
                }
        }
    }

    const int er = lane >> 2;
    const int ec = (lane & 3) * 2;
#pragma unroll
    for (int mt = 0; mt < 2; mt++) {
#pragma unroll
        for (int half = 0; half < 2; half++) {
            int gm = m0 + wm + mt * 16 + er + half * 8;
            if (gm < M) {
#pragma unroll
                for (int nt = 0; nt < 4; nt++) {
                    int cn = wn + nt * 8 + ec;
                    float v0 = c[mt][nt][half * 2 + 0] + s_bias[cn];
                    float v1 = c[mt][nt][half * 2 + 1] + s_bias[cn + 1];
                    if (ACT == 1) {
                        v0 = 0.5f * v0 * (1.f + erff(v0 * 0.70710678118654752f));
                        v1 = 0.5f * v1 * (1.f + erff(v1 * 0.70710678118654752f));
                    }
                    if (OUTMODE == 0) {
                        float2 o; o.x = v0; o.y = v1;
                        *(float2*)(C + (size_t)gm * ldc + n0 + cn) = o;
                    } else {
                        bf16 h0 = __float2bfloat16(v0);
                        bf16 h1 = __float2bfloat16(v1);
                        uint32_t H = pk_bf2(h0, h1);
                        uint32_t L = pk_bf2(__float2bfloat16(v0 - __bfloat162float(h0)),
                                            __float2bfloat16(v1 - __bfloat162float(h1)));
                        size_t o16 = (size_t)gm * ldc16 + n0 + cn;
                        *(uint32_t*)(Chi + o16) = H;
                        *(uint32_t*)(Clo + o16) = L;
                    }
                }
            }
        }
    }
}

// =======================================================================
// int8 split-3 GEMM (FFN1): C = sa*sb*(2^14*hh + 2^7*cross) + bias, GELU,
// write bf16 hi/lo. K=512, k-chunk 64 bytes, same smem geometry as bf16.
// =======================================================================
__global__ void __launch_bounds__(512, 1) mma_gemm_s8(
    const int8_t* __restrict__ Aqh, const int8_t* __restrict__ Aql,
    const int8_t* __restrict__ Bqh, const int8_t* __restrict__ Bql,
    const float* __restrict__ sa, const float* __restrict__ sb,
    const float* __restrict__ bias,
    bf16* __restrict__ Chi, bf16* __restrict__ Clo, int ldc16,
    int M, int K, int Nc)
{
    extern __shared__ char sm[];
    float* s_bias = (float*)(sm + 3 * STGB);
    float* s_sb   = s_bias + 128;

    const int tid  = threadIdx.x;
    const int wid  = tid >> 5;
    const int lane = tid & 31;
    const int m0 = blockIdx.y * 128;
    const int n0 = blockIdx.x * 128;
    const uint32_t sbase = smem_u32(sm);

    if (tid < 128) { s_bias[tid] = bias[n0 + tid]; s_sb[tid] = sb[n0 + tid]; }

    const int wm = (wid >> 2) * 32;
    const int wn = (wid & 3) * 32;
    const int lrow = (lane & 7) + ((lane >> 3) & 1) * 8;
    const int lcol = (lane >> 4) * 8;

    int chh[2][4][4], ccr[2][4][4];
#pragma unroll
    for (int i = 0; i < 2; i++)
#pragma unroll
        for (int j = 0; j < 4; j++)
#pragma unroll
            for (int r = 0; r < 4; r++) { chh[i][j][r] = 0; ccr[i][j][r] = 0; }

    const int nchunks = K >> 6;   // 64-byte chunks
    const char* srcs[4] = {(const char*)Aqh, (const char*)Aql,
                           (const char*)Bqh, (const char*)Bql};

    auto load_chunk = [&](int ch, int s) {
        const int k0b = ch * 64;
#pragma unroll
        for (int t = 0; t < 4; t++) {
            int idx  = tid + t * 512;
            int unit = idx & 3;
            int row  = (idx >> 2) & 127;
            int arr  = idx >> 9;
            int grow = (arr < 2) ? min(m0 + row, M - 1) : (n0 + row);
            const char* src = srcs[arr] + (size_t)grow * K + k0b + unit * 16;
            uint32_t dst = sbase + s * STGB + arr * ARRB + row * ROWB + unit * 16;
            cpa16(dst, src);
        }
        asm volatile("cp.async.commit_group;" ::: "memory");
    };

    load_chunk(0, 0);
    if (nchunks > 1) load_chunk(1, 1);

    for (int ch = 0; ch < nchunks; ch++) {
        if (ch + 1 < nchunks) {
            asm volatile("cp.async.wait_group 1;" ::: "memory");
        } else {
            asm volatile("cp.async.wait_group 0;" ::: "memory");
        }
        __syncthreads();
        if (ch + 2 < nchunks) load_chunk(ch + 2, (ch + 2) % 3);

        const int s = ch % 3;
        uint32_t sA_hi = sbase + s * STGB;
        uint32_t sA_lo = sA_hi + ARRB;
        uint32_t sB_hi = sA_lo + ARRB;
        uint32_t sB_lo = sB_hi + ARRB;

#pragma unroll
        for (int ks = 0; ks < 2; ks++) {          // two k32 steps per 64B chunk
            const int kk = ks * 16;               // b16-view column offset
            uint32_t ah[2][4], al[2][4], bh[4][2], bl[4][2];
#pragma unroll
            for (int mt = 0; mt < 2; mt++) {
                uint32_t off = (uint32_t)((wm + mt * 16 + lrow) * LDK + kk + lcol) * 2;
                ldsm4(ah[mt], sA_hi + off);
                ldsm4(al[mt], sA_lo + off);
            }
#pragma unroll
            for (int p = 0; p < 2; p++) {
                uint32_t off = (uint32_t)((wn + p * 16 + lrow) * LDK + kk + lcol) * 2;
                uint32_t t[4];
                ldsm4(t, sB_hi + off);
                bh[2 * p][0] = t[0]; bh[2 * p + 1][0] = t[1];
                bh[2 * p][1] = t[2]; bh[2 * p + 1][1] = t[3];
                ldsm4(t, sB_lo + off);
                bl[2 * p][0] = t[0]; bl[2 * p + 1][0] = t[1];
                bl[2 * p][1] = t[2]; bl[2 * p + 1][1] = t[3];
            }
#pragma unroll
            for (int mt = 0; mt < 2; mt++)
#pragma unroll
                for (int nt = 0; nt < 4; nt++) {
                    mma_s8(chh[mt][nt], ah[mt], bh[nt][0], bh[nt][1]);
                    mma_s8(ccr[mt][nt], ah[mt], bl[nt][0], bl[nt][1]);
                    mma_s8(ccr[mt][nt], al[mt], bh[nt][0], bh[nt][1]);
                }
        }
    }

    const int er = lane >> 2;
    const int ec = (lane & 3) * 2;
#pragma unroll
    for (int mt = 0; mt < 2; mt++) {
#pragma unroll
        for (int half = 0; half < 2; half++) {
            int gm = m0 + wm + mt * 16 + er + half * 8;
            if (gm < M) {
                float srow = sa[gm];
#pragma unroll
                for (int nt = 0; nt < 4; nt++) {
                    int cn = wn + nt * 8 + ec;
                    float v0 = srow * s_sb[cn] *
                               (16384.f * (float)chh[mt][nt][half * 2 + 0] +
                                  128.f * (float)ccr[mt][nt][half * 2 + 0]) + s_bias[cn];
                    float v1 = srow * s_sb[cn + 1] *
                               (16384.f * (float)chh[mt][nt][half * 2 + 1] +
                                  128.f * (float)ccr[mt][nt][half * 2 + 1]) + s_bias[cn + 1];
                    v0 = 0.5f * v0 * (1.f + erff(v0 * 0.70710678118654752f));
                    v1 = 0.5f * v1 * (1.f + erff(v1 * 0.70710678118654752f));
                    bf16 h0 = __float2bfloat16(v0);
                    bf16 h1 = __float2bfloat16(v1);
                    uint32_t H = pk_bf2(h0, h1);
                    uint32_t L = pk_bf2(__float2bfloat16(v0 - __bfloat162float(h0)),
                                        __float2bfloat16(v1 - __bfloat162float(h1)));
                    size_t o16 = (size_t)gm * ldc16 + n0 + cn;
                    *(uint32_t*)(Chi + o16) = H;
                    *(uint32_t*)(Clo + o16) = L;
                }
            }
        }
    }
}

// ---------------- zero init ----------------
__global__ void zero_kernel() {
    int i = blockIdx.x * blockDim.x + threadIdx.x;
    if (i < NN) { g_count[i] = 0; g_outdeg[i] = 0.f; }
}

// ---------------- edge kernel ----------------
__global__ void edge_kernel(const int* __restrict__ src, const int* __restrict__ dst) {
    int e = blockIdx.x * blockDim.x + threadIdx.x;
    if (e >= EE) return;
    int s = src[e], d = dst[e];
    atomicAdd(&g_count[d], 1);
    atomicAdd(&g_outdeg[s], 1.0f);

    float4 u0 = *(const float4*)(g_su + (size_t)s * 8);
    float4 u1 = *(const float4*)(g_su + (size_t)s * 8 + 4);
    float4 v0 = *(const float4*)(g_sv + (size_t)d * 8);
    float4 v1 = *(const float4*)(g_sv + (size_t)d * 8 + 4);
    float r[8] = {u0.x + v0.x, u0.y + v0.y, u0.z + v0.z, u0.w + v0.w,
                  u1.x + v1.x, u1.y + v1.y, u1.z + v1.z, u1.w + v1.w};
#pragma unroll
    for (int h = 0; h < 8; h++) {
        float x = r[h];
        x = (x > 0.f) ? x : 0.2f * x;
        r[h] = expf(x);
    }
    float4* out = (float4*)(g_ex + (size_t)e * 8);
    out[0] = make_float4(r[0], r[1], r[2], r[3]);
    out[1] = make_float4(r[4], r[5], r[6], r[7]);
}

// ---------------- parallel scan ----------------
__global__ void scan_a() {
    __shared__ int sh[1024];
    int tid = threadIdx.x;
    int i = blockIdx.x * 1024 + tid;
    int v = (i < NN) ? g_count[i] : 0;
    sh[tid] = v;
    __syncthreads();
#pragma unroll
    for (int o = 1; o < 1024; o <<= 1) {
        int t2 = (tid >= o) ? sh[tid - o] : 0;
        __syncthreads();
        sh[tid] += t2;
        __syncthreads();
    }
    if (i < NN) g_offsets[i + 1] = sh[tid];
    if (tid == 1023) g_bsum[blockIdx.x] = sh[1023];
}
__global__ void scan_b(int ntiles) {
    if (threadIdx.x == 0) {
        int run = 0;
        for (int i = 0; i < ntiles; i++) { int t = g_bsum[i]; g_bsum[i] = run; run += t; }
    }
}
__global__ void scan_c() {
    int i = blockIdx.x * 1024 + threadIdx.x;
    if (i >= NN) return;
    int base = g_bsum[i >> 10];
    int incl = g_offsets[i + 1];
    int v = g_count[i];
    g_offsets[i + 1] = base + incl;
    g_cursor[i] = base + incl - v;
    if (i == 0) g_offsets[0] = 0;
}

// ---------------- scatter (stores {edge, src}) ----------------
__global__ void scatter_kernel(const int* __restrict__ src, const int* __restrict__ dst) {
    int e = blockIdx.x * blockDim.x + threadIdx.x;
    if (e >= EE) return;
    int pos = atomicAdd(&g_cursor[dst[e]], 1);
    g_csr2[pos] = make_int2(e, src[e]);
}

// ---------------- message: warp-per-node, single pass, writes f32 cat ----------------
__global__ void __launch_bounds__(256) message2() {
    int warp = threadIdx.x >> 5, lane = threadIdx.x & 31;
    int n = blockIdx.x * 8 + warp;
    if (n >= NN) return;
    int off = g_offsets[n];
    int deg = g_offsets[n + 1] - off;
    float outdeg_n = g_outdeg[n];
    const int hd = (lane & 1) * 4;

    float a1[4] = {0.f, 0.f, 0.f, 0.f};
    float a2[4] = {0.f, 0.f, 0.f, 0.f};
    float a3[4] = {0.f, 0.f, 0.f, 0.f};
    float dn[4] = {0.f, 0.f, 0.f, 0.f};

    for (int base = 0; base < deg; base += 32) {
        int m = deg - base; if (m > 32) m = 32;
        int2  es = make_int2(0, 0);
        float nl = 0.f;
        if (lane < m) {
            es = g_csr2[off + base + lane];
            nl = rsqrtf(g_outdeg[es.y] * outdeg_n);
        }
        for (int j = 0; j < m; j++) {
            int   s  = __shfl_sync(0xffffffffu, es.y, j);
            int   e  = __shfl_sync(0xffffffffu, es.x, j);
            float nm = __shfl_sync(0xffffffffu, nl, j);
            float4 v = *(const float4*)(g_catf + (size_t)s * CATD + lane * 4);  // h row
            float4 w = *(const float4*)(g_ex + (size_t)e * 8 + hd);
            a1[0] += v.x * w.x; a1[1] += v.y * w.y; a1[2] += v.z * w.z; a1[3] += v.w * w.w;
            a2[0] += v.x;       a2[1] += v.y;       a2[2] += v.z;       a2[3] += v.w;
            a3[0] += v.x * nm;  a3[1] += v.y * nm;  a3[2] += v.z * nm;  a3[3] += v.w * nm;
            dn[0] += w.x;       dn[1] += w.y;       dn[2] += w.z;       dn[3] += w.w;
        }
    }

    float inv_indeg = 1.f / fmaxf((float)deg, 1.f);
    size_t rowb = (size_t)n * CATD;
    float4 o1, o2, o3;
    float* p1 = (float*)&o1; float* p2 = (float*)&o2; float* p3 = (float*)&o3;
#pragma unroll
    for (int q = 0; q < 4; q++) {
        float rq = (dn[q] > 0.f) ? (1.f / dn[q]) : 0.f;
        p1[q] = a1[q] * rq;
        p2[q] = a2[q] * inv_indeg;
        p3[q] = a3[q];
    }
    *(float4*)(g_catf + rowb + 128 + lane * 4) = o1;
    *(float4*)(g_catf + rowb + 256 + lane * 4) = o2;
    *(float4*)(g_catf + rowb + 384 + lane * 4) = o3;
}

// ---------------- launch ----------------
extern "C" void kernel_launch(void* const* d_in, const int* in_sizes, int n_in,
                              void* d_out, int out_size) {
    const float* x    = (const float*)d_in[0];
    const int*   src  = (const int*)  d_in[1];
    const int*   dst  = (const int*)  d_in[2];
    const float* fc_w = (const float*)d_in[3];
    const float* fc_b = (const float*)d_in[4];
    const float* au_w = (const float*)d_in[5];
    const float* au_b = (const float*)d_in[6];
    const float* av_w = (const float*)d_in[7];
    const float* w1   = (const float*)d_in[8];
    const float* b1   = (const float*)d_in[9];
    const float* w2   = (const float*)d_in[10];
    const float* b2   = (const float*)d_in[11];
    float* out = (float*)d_out;

    float *catf, *sca, *scw1;
    cudaGetSymbolAddress((void**)&catf, g_catf);
    cudaGetSymbolAddress((void**)&sca,  g_sca);
    cudaGetSymbolAddress((void**)&scw1, g_scw1);
    int8_t *catqh, *catql, *w1qh, *w1ql;
    cudaGetSymbolAddress((void**)&catqh, g_catqh); cudaGetSymbolAddress((void**)&catql, g_catql);
    cudaGetSymbolAddress((void**)&w1qh,  g_w1qh);  cudaGetSymbolAddress((void**)&w1ql,  g_w1ql);
    bf16 *x16h, *x16l, *fh, *fl, *fcwh, *fcwl, *w2h, *w2l;
    cudaGetSymbolAddress((void**)&x16h, g_x16h); cudaGetSymbolAddress((void**)&x16l, g_x16l);
    cudaGetSymbolAddress((void**)&fh,   g_fh);   cudaGetSymbolAddress((void**)&fl,   g_fl);
    cudaGetSymbolAddress((void**)&fcwh, g_fcwh); cudaGetSymbolAddress((void**)&fcwl, g_fcwl);
    cudaGetSymbolAddress((void**)&w2h,  g_w2h);  cudaGetSymbolAddress((void**)&w2l,  g_w2l);

    const int SMEM   = 3 * STGB + 512;
    const int SMEMS8 = 3 * STGB + 1024;
    cudaFuncSetAttribute(mma_gemm16<0, 0>, cudaFuncAttributeMaxDynamicSharedMemorySize, SMEM);
    cudaFuncSetAttribute(mma_gemm_s8,      cudaFuncAttributeMaxDynamicSharedMemorySize, SMEMS8);

    const int MT = (NN + 127) / 128;   // 391
    const int NT2 = (NN + 1023) / 1024; // 49

    cudaStream_t s2;
    cudaEvent_t ev0, ev1;
    cudaStreamCreateWithFlags(&s2, cudaStreamNonBlocking);
    cudaEventCreateWithFlags(&ev0, cudaEventDisableTiming);
    cudaEventCreateWithFlags(&ev1, cudaEventDisableTiming);

    // zero on main, fork
    zero_kernel<<<(NN + 255) / 256, 256>>>();
    cudaEventRecord(ev0, 0);
    cudaStreamWaitEvent(s2, ev0, 0);

    // Branch B: combo -> attn2 -> edge -> scan -> scatter -> w1 quant
    combo_w<<<16, 128, 0, s2>>>(fc_w, fc_b, au_w, au_b, av_w);
    attn2<<<(NN + 7) / 8, 256, 0, s2>>>(x);
    edge_kernel<<<(EE + 255) / 256, 256, 0, s2>>>(src, dst);
    scan_a<<<NT2, 1024, 0, s2>>>();
    scan_b<<<1, 32, 0, s2>>>(NT2);
    scan_c<<<NT2, 1024, 0, s2>>>();
    scatter_kernel<<<(EE + 255) / 256, 256, 0, s2>>>(src, dst);
    quant_rows<<<(HID * 32 + 255) / 256, 256, 0, s2>>>(w1, w1qh, w1ql, scw1, HID);
    cudaEventRecord(ev1, s2);

    // Branch A: split -> fc GEMM (h written into catf cols 0..127)
    split_all<<<(TOTF4 + 255) / 256, 256>>>(x, fc_w, w2);
    mma_gemm16<0, 0><<<dim3(1, MT), 512, SMEM>>>(
        x16h, x16l, fcwh, fcwl, fc_b, catf, CATD, nullptr, nullptr, 0, NN, DIM, DIM);

    // Join
    cudaStreamWaitEvent(0, ev1, 0);

    // message -> cat f32 complete -> quantize cat
    message2<<<(NN + 7) / 8, 256>>>();
    quant_rows<<<(NN * 32 + 255) / 256, 256>>>(catf, catqh, catql, sca, NN);

    // FFN1 int8 split-3 -> f bf16 hi/lo
    mma_gemm_s8<<<dim3(4, MT), 512, SMEMS8>>>(
        catqh, catql, w1qh, w1ql, sca, scw1, b1, fh, fl, HID, NN, CATD, HID);

    // FFN2 bf16x3 -> out
    mma_gemm16<0, 0><<<dim3(1, MT), 512, SMEM>>>(
        fh, fl, w2h, w2l, b2, out, DIM, nullptr, nullptr, 0, NN, HID, DIM);
}